// round 9
// baseline (speedup 1.0000x reference)
#include <cuda_runtime.h>
#include <cuda_fp16.h>
#include <math.h>

// Problem constants (fixed shapes per reference)
#define NN 98304      // total nodes = B * ACT
#define CC 64         // channels
#define EE 1572864    // edges
#define HH 32         // hidden
#define SCAN_BLKS 96  // NN / 1024

// ---------------- static device scratch (no allocation allowed) --------------
__device__ int     g_cnt[NN];        // in-degree (excl. self loop)
__device__ float   g_dinv[NN];       // rsqrt(deg+1)
__device__ int     g_rowptr[NN + 1]; // CSR offsets (by target/col)
__device__ int     g_pos[NN];        // scatter cursors
__device__ int     g_src[EE];        // CSR source-node indices
__device__ int     g_btot[SCAN_BLKS];// per-block totals
__device__ int     g_boff[SCAN_BLKS];// per-block exclusive offsets
__device__ __half2 g_xwh[NN * 32];   // state @ W_gcn, fp16 pairs (ch 2l,2l+1)
__device__ __half2 g_hh[NN * 32];    // relu(gcn)+state, fp16 pairs
__device__ float   g_sum;            // global softplus sum

// ---------------- kernels ----------------------------------------------------

// 4 edges per thread via one int4 load; atomicAdd w/o return -> REDG.
__global__ void k_count(const int4* __restrict__ col4) {
    int e = blockIdx.x * blockDim.x + threadIdx.x;
    if (e < EE / 4) {
        int4 c = col4[e];
        atomicAdd(&g_cnt[c.x], 1);
        atomicAdd(&g_cnt[c.y], 1);
        atomicAdd(&g_cnt[c.z], 1);
        atomicAdd(&g_cnt[c.w], 1);
    }
}

// Phase 1: per-block exclusive scan (1024 elems/block), block totals, dinv.
__global__ void k_scan1() {
    __shared__ int wsum[32];
    int t = threadIdx.x;
    int lane = t & 31, warp = t >> 5;
    int i = blockIdx.x * 1024 + t;
    int c = g_cnt[i];
    int x = c;
    #pragma unroll
    for (int off = 1; off < 32; off <<= 1) {
        int y = __shfl_up_sync(0xffffffffu, x, off);
        if (lane >= off) x += y;
    }
    if (lane == 31) wsum[warp] = x;
    __syncthreads();
    if (warp == 0) {
        int s = wsum[lane];
        #pragma unroll
        for (int off = 1; off < 32; off <<= 1) {
            int y = __shfl_up_sync(0xffffffffu, s, off);
            if (lane >= off) s += y;
        }
        wsum[lane] = s;   // inclusive over warps
    }
    __syncthreads();
    int excl = x - c + (warp > 0 ? wsum[warp - 1] : 0);
    g_rowptr[i] = excl;                       // block-local for now
    g_dinv[i]   = rsqrtf((float)(c + 1));
    if (t == 1023) g_btot[blockIdx.x] = excl + c;
}

// Phase 2: single small block scans the 96 block totals -> exclusive offsets.
__global__ void k_scan2() {
    __shared__ int s[128];
    int t = threadIdx.x;
    int v = (t < SCAN_BLKS) ? g_btot[t] : 0;
    s[t] = v;
    __syncthreads();
    for (int off = 1; off < 128; off <<= 1) {
        int a = (t >= off) ? s[t - off] : 0;
        __syncthreads();
        s[t] += a;
        __syncthreads();
    }
    if (t < SCAN_BLKS) g_boff[t] = s[t] - v;  // exclusive
    if (t == 127) g_rowptr[NN] = EE;
}

// Phase 3: add block offsets, init cursors.
__global__ void k_scan3() {
    int i = blockIdx.x * 1024 + threadIdx.x;
    int v = g_rowptr[i] + g_boff[blockIdx.x];
    g_rowptr[i] = v;
    g_pos[i]    = v;
}

// 4 edges per thread; int4 loads of row+col halve edge-list LDG traffic.
__global__ void k_scatter(const int4* __restrict__ row4, const int4* __restrict__ col4) {
    int e = blockIdx.x * blockDim.x + threadIdx.x;
    if (e < EE / 4) {
        int4 r = row4[e];
        int4 c = col4[e];
        g_src[atomicAdd(&g_pos[c.x], 1)] = r.x;
        g_src[atomicAdd(&g_pos[c.y], 1)] = r.y;
        g_src[atomicAdd(&g_pos[c.z], 1)] = r.z;
        g_src[atomicAdd(&g_pos[c.w], 1)] = r.w;
    }
}

// xw = state @ W_gcn ; warp-per-node, W in SMEM.
// Lane l computes output channels 2l and 2l+1 -> weight pair via one LDS.64.
__global__ void k_xw(const float* __restrict__ state, const float* __restrict__ Wg) {
    __shared__ float Ws[CC * CC];   // 16 KB, row-major W[k][c]
    int t = threadIdx.x;
    for (int i = t; i < CC * CC; i += blockDim.x) Ws[i] = Wg[i];
    __syncthreads();
    const float2* Ws2 = (const float2*)Ws;   // Ws2[k*32 + l] = (W[k][2l], W[k][2l+1])
    int lane = t & 31;
    int n = blockIdx.x * (blockDim.x >> 5) + (t >> 5);
    float x0 = state[n * CC + lane];
    float x1 = state[n * CC + 32 + lane];
    float a0 = 0.f, a1 = 0.f;
    #pragma unroll
    for (int k = 0; k < 32; k++) {
        float v = __shfl_sync(0xffffffffu, x0, k);
        float2 w = Ws2[k * 32 + lane];
        a0 += v * w.x;
        a1 += v * w.y;
    }
    #pragma unroll
    for (int k = 0; k < 32; k++) {
        float v = __shfl_sync(0xffffffffu, x1, k);
        float2 w = Ws2[(k + 32) * 32 + lane];
        a0 += v * w.x;
        a1 += v * w.y;
    }
    g_xwh[n * 32 + lane] = __floats2half2_rn(a0, a1);
}

// Pull-style aggregation + GCN epilogue. Warp per node, no atomics.
// Lane l handles channels 2l,2l+1 via ONE half2 (LDG.32) per edge -> 128B/edge.
__global__ void k_gather(const float* __restrict__ state, const float* __restrict__ b_gcn) {
    int t = threadIdx.x;
    int lane = t & 31;
    int n = blockIdx.x * (blockDim.x >> 5) + (t >> 5);
    int j   = g_rowptr[n];
    int end = g_rowptr[n + 1];
    float acc0 = 0.f, acc1 = 0.f;

    for (; j + 4 <= end; j += 4) {
        int sA = g_src[j];
        int sB = g_src[j + 1];
        int sC = g_src[j + 2];
        int sD = g_src[j + 3];
        float wA = g_dinv[sA];
        float wB = g_dinv[sB];
        float wC = g_dinv[sC];
        float wD = g_dinv[sD];
        float2 vA = __half22float2(g_xwh[sA * 32 + lane]);
        float2 vB = __half22float2(g_xwh[sB * 32 + lane]);
        float2 vC = __half22float2(g_xwh[sC * 32 + lane]);
        float2 vD = __half22float2(g_xwh[sD * 32 + lane]);
        acc0 += wA * vA.x + wB * vB.x + wC * vC.x + wD * vD.x;
        acc1 += wA * vA.y + wB * vB.y + wC * vC.y + wD * vD.y;
    }
    for (; j < end; j++) {
        int s = g_src[j];
        float w = g_dinv[s];
        float2 v = __half22float2(g_xwh[s * 32 + lane]);
        acc0 += w * v.x;
        acc1 += w * v.y;
    }

    float dn = g_dinv[n];
    float2 self = __half22float2(g_xwh[n * 32 + lane]);
    float2 b  = ((const float2*)b_gcn)[lane];          // (b[2l], b[2l+1])
    float2 st = ((const float2*)state)[n * 32 + lane]; // (state[2l], state[2l+1])
    float o0 = dn * (acc0 + dn * self.x) + b.x;
    float o1 = dn * (acc1 + dn * self.y) + b.y;
    o0 = fmaxf(o0, 0.f) + st.x;
    o1 = fmaxf(o1, 0.f) + st.y;
    g_hh[n * 32 + lane] = __floats2half2_rn(o0, o1);
}

// Fused MLP 64->32->32->1 + softplus; writes conc to out, block-reduced sum.
// h channels 2l,2l+1 live in lane l as a half2.
__global__ void k_mlp(const float* __restrict__ W1, const float* __restrict__ b1,
                      const float* __restrict__ W2, const float* __restrict__ b2,
                      const float* __restrict__ W3, const float* __restrict__ b3,
                      float* __restrict__ out) {
    __shared__ float W1s[CC * HH];   // 8 KB, W1[k][j]
    __shared__ float W2s[HH * HH];   // 4 KB
    __shared__ float W3s[HH], b1s[HH], b2s[HH];
    __shared__ float b3s;
    __shared__ float wsum[4];
    int t = threadIdx.x;
    for (int i = t; i < CC * HH; i += 128) W1s[i] = W1[i];
    for (int i = t; i < HH * HH; i += 128) W2s[i] = W2[i];
    if (t < HH) { W3s[t] = W3[t]; b1s[t] = b1[t]; b2s[t] = b2[t]; }
    if (t == 0) b3s = b3[0];
    __syncthreads();

    int lane = t & 31, warp = t >> 5;
    int gw = blockIdx.x * 4 + warp;
    int nwarps = gridDim.x * 4;
    float lsum = 0.f;

    for (int n = gw; n < NN; n += nwarps) {
        float2 x = __half22float2(g_hh[n * 32 + lane]);  // ch 2*lane, 2*lane+1
        float a1 = b1s[lane];
        #pragma unroll
        for (int j = 0; j < 32; j++) {
            float vx = __shfl_sync(0xffffffffu, x.x, j);
            float vy = __shfl_sync(0xffffffffu, x.y, j);
            a1 += vx * W1s[(2 * j)     * HH + lane];
            a1 += vy * W1s[(2 * j + 1) * HH + lane];
        }
        a1 = (a1 > 0.f) ? a1 : 0.01f * a1;

        float a2 = b2s[lane];
        #pragma unroll
        for (int k = 0; k < 32; k++)
            a2 += __shfl_sync(0xffffffffu, a1, k) * W2s[k * HH + lane];
        a2 = (a2 > 0.f) ? a2 : 0.01f * a2;

        float p = a2 * W3s[lane];
        #pragma unroll
        for (int o = 16; o > 0; o >>= 1) p += __shfl_xor_sync(0xffffffffu, p, o);

        if (lane == 0) {
            float z = p + b3s;
            float sp = fmaxf(z, 0.f) + log1pf(expf(-fabsf(z)));  // stable softplus
            out[n] = sp;
            lsum += sp;
        }
    }
    if (lane == 0) wsum[warp] = lsum;
    __syncthreads();
    if (t == 0) atomicAdd(&g_sum, wsum[0] + wsum[1] + wsum[2] + wsum[3]);
}

__global__ void k_norm(float* __restrict__ out) {
    int i = blockIdx.x * blockDim.x + threadIdx.x;
    if (i < NN) {
        float r = __frcp_rn(g_sum + 1e-20f);
        out[i] = out[i] * r;
    }
}

// ---------------- launch ------------------------------------------------------

extern "C" void kernel_launch(void* const* d_in, const int* in_sizes, int n_in,
                              void* d_out, int out_size) {
    const float* state = (const float*)d_in[0];
    const int*   ei    = (const int*)  d_in[1];   // [2, E]
    const float* Wg    = (const float*)d_in[2];
    const float* bg    = (const float*)d_in[3];
    const float* W1    = (const float*)d_in[4];
    const float* b1    = (const float*)d_in[5];
    const float* W2    = (const float*)d_in[6];
    const float* b2    = (const float*)d_in[7];
    const float* W3    = (const float*)d_in[8];
    const float* b3    = (const float*)d_in[9];
    float* out = (float*)d_out;

    const int* row = ei;        // sources
    const int* col = ei + EE;   // targets

    void* p_cnt = 0; void* p_sum = 0;
    cudaGetSymbolAddress(&p_cnt, g_cnt);
    cudaGetSymbolAddress(&p_sum, g_sum);
    cudaMemsetAsync(p_cnt, 0, NN * sizeof(int), 0);
    cudaMemsetAsync(p_sum, 0, sizeof(float), 0);

    k_count  <<<EE / 4 / 256, 256>>>((const int4*)col);
    k_xw     <<<NN / 8,   256>>>(state, Wg);     // 8 warps/block, warp-per-node
    k_scan1  <<<SCAN_BLKS, 1024>>>();
    k_scan2  <<<1, 128>>>();
    k_scan3  <<<SCAN_BLKS, 1024>>>();
    k_scatter<<<EE / 4 / 256, 256>>>((const int4*)row, (const int4*)col);
    k_gather <<<NN / 8,   256>>>(state, bg);
    k_mlp    <<<592, 128>>>(W1, b1, W2, b2, W3, b3, out);
    k_norm   <<<NN / 256, 256>>>(out);
}

// round 10
// speedup vs baseline: 1.5414x; 1.5414x over previous
#include <cuda_runtime.h>
#include <cuda_fp16.h>
#include <math.h>

// Problem constants (fixed shapes per reference)
#define NN 98304      // total nodes = B * ACT
#define CC 64         // channels
#define EE 1572864    // edges
#define HH 32         // hidden
#define SCAN_BLKS 96  // NN / 1024

// ---------------- static device scratch (no allocation allowed) --------------
__device__ int     g_cnt[NN];        // in-degree (excl. self loop)
__device__ float   g_dinv[NN];       // rsqrt(deg+1)
__device__ int     g_rowptr[NN + 1]; // CSR offsets (by target/col)
__device__ int     g_pos[NN];        // scatter cursors
__device__ int     g_src[EE];        // CSR source-node indices
__device__ int     g_btot[SCAN_BLKS];// per-block totals
__device__ int     g_boff[SCAN_BLKS];// per-block exclusive offsets
__device__ __half2 g_xwh[NN * 32];   // state @ W_gcn, fp16 pairs (ch 2l,2l+1)
__device__ __half2 g_hh[NN * 32];    // relu(gcn)+state, fp16 pairs
__device__ float   g_sum;            // global softplus sum

// ---------------- kernels ----------------------------------------------------

// 4 edges per thread via one int4 load; atomicAdd w/o return -> REDG.
__global__ void k_count(const int4* __restrict__ col4) {
    int e = blockIdx.x * blockDim.x + threadIdx.x;
    if (e < EE / 4) {
        int4 c = col4[e];
        atomicAdd(&g_cnt[c.x], 1);
        atomicAdd(&g_cnt[c.y], 1);
        atomicAdd(&g_cnt[c.z], 1);
        atomicAdd(&g_cnt[c.w], 1);
    }
}

// Phase 1: per-block exclusive scan (1024 elems/block), block totals, dinv.
__global__ void k_scan1() {
    __shared__ int wsum[32];
    int t = threadIdx.x;
    int lane = t & 31, warp = t >> 5;
    int i = blockIdx.x * 1024 + t;
    int c = g_cnt[i];
    int x = c;
    #pragma unroll
    for (int off = 1; off < 32; off <<= 1) {
        int y = __shfl_up_sync(0xffffffffu, x, off);
        if (lane >= off) x += y;
    }
    if (lane == 31) wsum[warp] = x;
    __syncthreads();
    if (warp == 0) {
        int s = wsum[lane];
        #pragma unroll
        for (int off = 1; off < 32; off <<= 1) {
            int y = __shfl_up_sync(0xffffffffu, s, off);
            if (lane >= off) s += y;
        }
        wsum[lane] = s;   // inclusive over warps
    }
    __syncthreads();
    int excl = x - c + (warp > 0 ? wsum[warp - 1] : 0);
    g_rowptr[i] = excl;                       // block-local for now
    g_dinv[i]   = rsqrtf((float)(c + 1));
    if (t == 1023) g_btot[blockIdx.x] = excl + c;
}

// Phase 2: single small block scans the 96 block totals -> exclusive offsets.
__global__ void k_scan2() {
    __shared__ int s[128];
    int t = threadIdx.x;
    int v = (t < SCAN_BLKS) ? g_btot[t] : 0;
    s[t] = v;
    __syncthreads();
    for (int off = 1; off < 128; off <<= 1) {
        int a = (t >= off) ? s[t - off] : 0;
        __syncthreads();
        s[t] += a;
        __syncthreads();
    }
    if (t < SCAN_BLKS) g_boff[t] = s[t] - v;  // exclusive
    if (t == 127) g_rowptr[NN] = EE;
}

// Phase 3: add block offsets, init cursors.
__global__ void k_scan3() {
    int i = blockIdx.x * 1024 + threadIdx.x;
    int v = g_rowptr[i] + g_boff[blockIdx.x];
    g_rowptr[i] = v;
    g_pos[i]    = v;
}

// 4 edges per thread; int4 loads of row+col halve edge-list LDG traffic.
__global__ void k_scatter(const int4* __restrict__ row4, const int4* __restrict__ col4) {
    int e = blockIdx.x * blockDim.x + threadIdx.x;
    if (e < EE / 4) {
        int4 r = row4[e];
        int4 c = col4[e];
        g_src[atomicAdd(&g_pos[c.x], 1)] = r.x;
        g_src[atomicAdd(&g_pos[c.y], 1)] = r.y;
        g_src[atomicAdd(&g_pos[c.z], 1)] = r.z;
        g_src[atomicAdd(&g_pos[c.w], 1)] = r.w;
    }
}

// xw = state @ W_gcn ; warp-per-node, W in SMEM.
// Lane l computes output channels 2l and 2l+1 -> weight pair via one LDS.64.
__global__ void k_xw(const float* __restrict__ state, const float* __restrict__ Wg) {
    __shared__ float Ws[CC * CC];   // 16 KB, row-major W[k][c]
    int t = threadIdx.x;
    for (int i = t; i < CC * CC; i += blockDim.x) Ws[i] = Wg[i];
    __syncthreads();
    const float2* Ws2 = (const float2*)Ws;   // Ws2[k*32 + l] = (W[k][2l], W[k][2l+1])
    int lane = t & 31;
    int n = blockIdx.x * (blockDim.x >> 5) + (t >> 5);
    float x0 = state[n * CC + lane];
    float x1 = state[n * CC + 32 + lane];
    float a0 = 0.f, a1 = 0.f;
    #pragma unroll
    for (int k = 0; k < 32; k++) {
        float v = __shfl_sync(0xffffffffu, x0, k);
        float2 w = Ws2[k * 32 + lane];
        a0 += v * w.x;
        a1 += v * w.y;
    }
    #pragma unroll
    for (int k = 0; k < 32; k++) {
        float v = __shfl_sync(0xffffffffu, x1, k);
        float2 w = Ws2[(k + 32) * 32 + lane];
        a0 += v * w.x;
        a1 += v * w.y;
    }
    g_xwh[n * 32 + lane] = __floats2half2_rn(a0, a1);
}

// Pull-style aggregation + GCN epilogue. Warp per node, no atomics.
// Lane l handles channels 2l,2l+1 via ONE half2 (LDG.32) per edge -> 128B/edge.
__global__ void k_gather(const float* __restrict__ state, const float* __restrict__ b_gcn) {
    int t = threadIdx.x;
    int lane = t & 31;
    int n = blockIdx.x * (blockDim.x >> 5) + (t >> 5);
    int j   = g_rowptr[n];
    int end = g_rowptr[n + 1];
    float acc0 = 0.f, acc1 = 0.f;

    for (; j + 4 <= end; j += 4) {
        int sA = g_src[j];
        int sB = g_src[j + 1];
        int sC = g_src[j + 2];
        int sD = g_src[j + 3];
        float wA = g_dinv[sA];
        float wB = g_dinv[sB];
        float wC = g_dinv[sC];
        float wD = g_dinv[sD];
        float2 vA = __half22float2(g_xwh[sA * 32 + lane]);
        float2 vB = __half22float2(g_xwh[sB * 32 + lane]);
        float2 vC = __half22float2(g_xwh[sC * 32 + lane]);
        float2 vD = __half22float2(g_xwh[sD * 32 + lane]);
        acc0 += wA * vA.x + wB * vB.x + wC * vC.x + wD * vD.x;
        acc1 += wA * vA.y + wB * vB.y + wC * vC.y + wD * vD.y;
    }
    for (; j < end; j++) {
        int s = g_src[j];
        float w = g_dinv[s];
        float2 v = __half22float2(g_xwh[s * 32 + lane]);
        acc0 += w * v.x;
        acc1 += w * v.y;
    }

    float dn = g_dinv[n];
    float2 self = __half22float2(g_xwh[n * 32 + lane]);
    float2 b  = ((const float2*)b_gcn)[lane];          // (b[2l], b[2l+1])
    float2 st = ((const float2*)state)[n * 32 + lane]; // (state[2l], state[2l+1])
    float o0 = dn * (acc0 + dn * self.x) + b.x;
    float o1 = dn * (acc1 + dn * self.y) + b.y;
    o0 = fmaxf(o0, 0.f) + st.x;
    o1 = fmaxf(o1, 0.f) + st.y;
    g_hh[n * 32 + lane] = __floats2half2_rn(o0, o1);
}

// Fused MLP 64->32->32->1 + softplus; writes conc to out, block-reduced sum.
// h channels 2l,2l+1 live in lane l as a half2.
__global__ void k_mlp(const float* __restrict__ W1, const float* __restrict__ b1,
                      const float* __restrict__ W2, const float* __restrict__ b2,
                      const float* __restrict__ W3, const float* __restrict__ b3,
                      float* __restrict__ out) {
    __shared__ float W1s[CC * HH];   // 8 KB, W1[k][j]
    __shared__ float W2s[HH * HH];   // 4 KB
    __shared__ float W3s[HH], b1s[HH], b2s[HH];
    __shared__ float b3s;
    __shared__ float wsum[4];
    int t = threadIdx.x;
    for (int i = t; i < CC * HH; i += 128) W1s[i] = W1[i];
    for (int i = t; i < HH * HH; i += 128) W2s[i] = W2[i];
    if (t < HH) { W3s[t] = W3[t]; b1s[t] = b1[t]; b2s[t] = b2[t]; }
    if (t == 0) b3s = b3[0];
    __syncthreads();

    int lane = t & 31, warp = t >> 5;
    int gw = blockIdx.x * 4 + warp;
    int nwarps = gridDim.x * 4;
    float lsum = 0.f;

    for (int n = gw; n < NN; n += nwarps) {
        float2 x = __half22float2(g_hh[n * 32 + lane]);  // ch 2*lane, 2*lane+1
        float a1 = b1s[lane];
        #pragma unroll
        for (int j = 0; j < 32; j++) {
            float vx = __shfl_sync(0xffffffffu, x.x, j);
            float vy = __shfl_sync(0xffffffffu, x.y, j);
            a1 += vx * W1s[(2 * j)     * HH + lane];
            a1 += vy * W1s[(2 * j + 1) * HH + lane];
        }
        a1 = (a1 > 0.f) ? a1 : 0.01f * a1;

        float a2 = b2s[lane];
        #pragma unroll
        for (int k = 0; k < 32; k++)
            a2 += __shfl_sync(0xffffffffu, a1, k) * W2s[k * HH + lane];
        a2 = (a2 > 0.f) ? a2 : 0.01f * a2;

        float p = a2 * W3s[lane];
        #pragma unroll
        for (int o = 16; o > 0; o >>= 1) p += __shfl_xor_sync(0xffffffffu, p, o);

        if (lane == 0) {
            float z = p + b3s;
            float sp = fmaxf(z, 0.f) + log1pf(expf(-fabsf(z)));  // stable softplus
            out[n] = sp;
            lsum += sp;
        }
    }
    if (lane == 0) wsum[warp] = lsum;
    __syncthreads();
    if (t == 0) atomicAdd(&g_sum, wsum[0] + wsum[1] + wsum[2] + wsum[3]);
}

__global__ void k_norm(float* __restrict__ out) {
    int i = blockIdx.x * blockDim.x + threadIdx.x;
    if (i < NN) {
        float r = __frcp_rn(g_sum + 1e-20f);
        out[i] = out[i] * r;
    }
}

// ---------------- launch ------------------------------------------------------

extern "C" void kernel_launch(void* const* d_in, const int* in_sizes, int n_in,
                              void* d_out, int out_size) {
    const float* state = (const float*)d_in[0];
    const int*   ei    = (const int*)  d_in[1];   // [2, E]
    const float* Wg    = (const float*)d_in[2];
    const float* bg    = (const float*)d_in[3];
    const float* W1    = (const float*)d_in[4];
    const float* b1    = (const float*)d_in[5];
    const float* W2    = (const float*)d_in[6];
    const float* b2    = (const float*)d_in[7];
    const float* W3    = (const float*)d_in[8];
    const float* b3    = (const float*)d_in[9];
    float* out = (float*)d_out;

    const int* row = ei;        // sources
    const int* col = ei + EE;   // targets

    void* p_cnt = 0; void* p_sum = 0;
    cudaGetSymbolAddress(&p_cnt, g_cnt);
    cudaGetSymbolAddress(&p_sum, g_sum);
    cudaMemsetAsync(p_cnt, 0, NN * sizeof(int), 0);
    cudaMemsetAsync(p_sum, 0, sizeof(float), 0);

    k_count  <<<EE / 4 / 256, 256>>>((const int4*)col);
    k_xw     <<<NN / 8,   256>>>(state, Wg);     // 8 warps/block, warp-per-node
    k_scan1  <<<SCAN_BLKS, 1024>>>();
    k_scan2  <<<1, 128>>>();
    k_scan3  <<<SCAN_BLKS, 1024>>>();
    k_scatter<<<EE / 4 / 256, 256>>>((const int4*)row, (const int4*)col);
    k_gather <<<NN / 8,   256>>>(state, bg);
    k_mlp    <<<592, 128>>>(W1, b1, W2, b2, W3, b3, out);
    k_norm   <<<NN / 256, 256>>>(out);
}

// round 13
// speedup vs baseline: 1.5877x; 1.0300x over previous
#include <cuda_runtime.h>
#include <cuda_fp16.h>
#include <math.h>

// Problem constants (fixed shapes per reference)
#define NN 98304      // total nodes = B * ACT
#define CC 64         // channels
#define EE 1572864    // edges
#define HH 32         // hidden
#define SCAN_BLKS 96  // NN / 1024

// ---------------- static device scratch (no allocation allowed) --------------
__device__ int     g_cnt[NN];        // in-degree (excl. self loop)
__device__ float   g_dinv[NN];       // rsqrt(deg+1)
__device__ int     g_rowptr[NN];     // CSR offsets, BLOCK-LOCAL (add g_boff[i>>10])
__device__ int     g_pos[NN];        // scatter cursors, BLOCK-LOCAL
__device__ int     g_src[EE];        // CSR source-node indices
__device__ int     g_btot[SCAN_BLKS];// per-block totals
__device__ int     g_boff[SCAN_BLKS];// per-block exclusive offsets
__device__ __half2 g_xwh[NN * 32];   // state @ W_gcn, fp16 pairs (ch 2l,2l+1)
__device__ __half2 g_hh[NN * 32];    // relu(gcn)+state, fp16 pairs
__device__ float   g_sum;            // global softplus sum

// ---------------- kernels ----------------------------------------------------

// xw = state @ W_gcn ; warp-per-node, W in SMEM. Runs FIRST; also zeroes
// g_cnt / g_sum (no dependence on edge data).
__global__ void k_xw(const float* __restrict__ state, const float* __restrict__ Wg) {
    __shared__ float Ws[CC * CC];   // 16 KB, row-major W[k][c]
    int t = threadIdx.x;
    int gid = blockIdx.x * blockDim.x + t;
    if (gid < NN) g_cnt[gid] = 0;
    if (gid == 0) g_sum = 0.0f;
    for (int i = t; i < CC * CC; i += blockDim.x) Ws[i] = Wg[i];
    __syncthreads();
    const float2* Ws2 = (const float2*)Ws;   // Ws2[k*32 + l] = (W[k][2l], W[k][2l+1])
    int lane = t & 31;
    int n = blockIdx.x * (blockDim.x >> 5) + (t >> 5);
    float x0 = state[n * CC + lane];
    float x1 = state[n * CC + 32 + lane];
    float a0 = 0.f, a1 = 0.f;
    #pragma unroll
    for (int k = 0; k < 32; k++) {
        float v = __shfl_sync(0xffffffffu, x0, k);
        float2 w = Ws2[k * 32 + lane];
        a0 += v * w.x;
        a1 += v * w.y;
    }
    #pragma unroll
    for (int k = 0; k < 32; k++) {
        float v = __shfl_sync(0xffffffffu, x1, k);
        float2 w = Ws2[(k + 32) * 32 + lane];
        a0 += v * w.x;
        a1 += v * w.y;
    }
    g_xwh[n * 32 + lane] = __floats2half2_rn(a0, a1);
}

// 4 edges per thread via one int4 load; atomicAdd w/o return -> REDG.
__global__ void k_count(const int4* __restrict__ col4) {
    int e = blockIdx.x * blockDim.x + threadIdx.x;
    if (e < EE / 4) {
        int4 c = col4[e];
        atomicAdd(&g_cnt[c.x], 1);
        atomicAdd(&g_cnt[c.y], 1);
        atomicAdd(&g_cnt[c.z], 1);
        atomicAdd(&g_cnt[c.w], 1);
    }
}

// Phase 1: per-block exclusive scan (1024 elems/block), block totals, dinv,
// block-local rowptr AND cursor init (no scan3 needed).
__global__ void k_scan1() {
    __shared__ int wsum[32];
    int t = threadIdx.x;
    int lane = t & 31, warp = t >> 5;
    int i = blockIdx.x * 1024 + t;
    int c = g_cnt[i];
    int x = c;
    #pragma unroll
    for (int off = 1; off < 32; off <<= 1) {
        int y = __shfl_up_sync(0xffffffffu, x, off);
        if (lane >= off) x += y;
    }
    if (lane == 31) wsum[warp] = x;
    __syncthreads();
    if (warp == 0) {
        int s = wsum[lane];
        #pragma unroll
        for (int off = 1; off < 32; off <<= 1) {
            int y = __shfl_up_sync(0xffffffffu, s, off);
            if (lane >= off) s += y;
        }
        wsum[lane] = s;   // inclusive over warps
    }
    __syncthreads();
    int excl = x - c + (warp > 0 ? wsum[warp - 1] : 0);
    g_rowptr[i] = excl;                       // block-local
    g_pos[i]    = excl;                       // block-local cursor
    g_dinv[i]   = rsqrtf((float)(c + 1));
    if (t == 1023) g_btot[blockIdx.x] = excl + c;
}

// Phase 2: single small block scans the 96 block totals -> exclusive offsets.
__global__ void k_scan2() {
    __shared__ int s[128];
    int t = threadIdx.x;
    int v = (t < SCAN_BLKS) ? g_btot[t] : 0;
    s[t] = v;
    __syncthreads();
    for (int off = 1; off < 128; off <<= 1) {
        int a = (t >= off) ? s[t - off] : 0;
        __syncthreads();
        s[t] += a;
        __syncthreads();
    }
    if (t < SCAN_BLKS) g_boff[t] = s[t] - v;  // exclusive
}

// 4 edges per thread; local cursor + block offset -> global CSR slot.
__global__ void k_scatter(const int4* __restrict__ row4, const int4* __restrict__ col4) {
    int e = blockIdx.x * blockDim.x + threadIdx.x;
    if (e < EE / 4) {
        int4 r = row4[e];
        int4 c = col4[e];
        g_src[atomicAdd(&g_pos[c.x], 1) + g_boff[c.x >> 10]] = r.x;
        g_src[atomicAdd(&g_pos[c.y], 1) + g_boff[c.y >> 10]] = r.y;
        g_src[atomicAdd(&g_pos[c.z], 1) + g_boff[c.z >> 10]] = r.z;
        g_src[atomicAdd(&g_pos[c.w], 1) + g_boff[c.w >> 10]] = r.w;
    }
}

// Pull-style aggregation + GCN epilogue. Warp per node, no atomics.
// Lane l handles channels 2l,2l+1 via ONE half2 (LDG.32) per edge -> 128B/edge.
__global__ void k_gather(const float* __restrict__ state, const float* __restrict__ b_gcn) {
    int t = threadIdx.x;
    int lane = t & 31;
    int n = blockIdx.x * (blockDim.x >> 5) + (t >> 5);
    int j   = g_rowptr[n] + g_boff[n >> 10];
    int end = (n == NN - 1) ? EE : (g_rowptr[n + 1] + g_boff[(n + 1) >> 10]);
    float acc0 = 0.f, acc1 = 0.f;

    for (; j + 4 <= end; j += 4) {
        int sA = g_src[j];
        int sB = g_src[j + 1];
        int sC = g_src[j + 2];
        int sD = g_src[j + 3];
        float wA = g_dinv[sA];
        float wB = g_dinv[sB];
        float wC = g_dinv[sC];
        float wD = g_dinv[sD];
        float2 vA = __half22float2(g_xwh[sA * 32 + lane]);
        float2 vB = __half22float2(g_xwh[sB * 32 + lane]);
        float2 vC = __half22float2(g_xwh[sC * 32 + lane]);
        float2 vD = __half22float2(g_xwh[sD * 32 + lane]);
        acc0 += wA * vA.x + wB * vB.x + wC * vC.x + wD * vD.x;
        acc1 += wA * vA.y + wB * vB.y + wC * vC.y + wD * vD.y;
    }
    for (; j < end; j++) {
        int s = g_src[j];
        float w = g_dinv[s];
        float2 v = __half22float2(g_xwh[s * 32 + lane]);
        acc0 += w * v.x;
        acc1 += w * v.y;
    }

    float dn = g_dinv[n];
    float2 self = __half22float2(g_xwh[n * 32 + lane]);
    float2 b  = ((const float2*)b_gcn)[lane];          // (b[2l], b[2l+1])
    float2 st = ((const float2*)state)[n * 32 + lane]; // (state[2l], state[2l+1])
    float o0 = dn * (acc0 + dn * self.x) + b.x;
    float o1 = dn * (acc1 + dn * self.y) + b.y;
    o0 = fmaxf(o0, 0.f) + st.x;
    o1 = fmaxf(o1, 0.f) + st.y;
    g_hh[n * 32 + lane] = __floats2half2_rn(o0, o1);
}

// Fused MLP 64->32->32->1 + softplus; writes conc to out, block-reduced sum.
// h channels 2l,2l+1 live in lane l as a half2.
__global__ void k_mlp(const float* __restrict__ W1, const float* __restrict__ b1,
                      const float* __restrict__ W2, const float* __restrict__ b2,
                      const float* __restrict__ W3, const float* __restrict__ b3,
                      float* __restrict__ out) {
    __shared__ float W1s[CC * HH];   // 8 KB, W1[k][j]
    __shared__ float W2s[HH * HH];   // 4 KB
    __shared__ float W3s[HH], b1s[HH], b2s[HH];
    __shared__ float b3s;
    __shared__ float wsum[4];
    int t = threadIdx.x;
    for (int i = t; i < CC * HH; i += 128) W1s[i] = W1[i];
    for (int i = t; i < HH * HH; i += 128) W2s[i] = W2[i];
    if (t < HH) { W3s[t] = W3[t]; b1s[t] = b1[t]; b2s[t] = b2[t]; }
    if (t == 0) b3s = b3[0];
    __syncthreads();

    int lane = t & 31, warp = t >> 5;
    int gw = blockIdx.x * 4 + warp;
    int nwarps = gridDim.x * 4;
    float lsum = 0.f;

    for (int n = gw; n < NN; n += nwarps) {
        float2 x = __half22float2(g_hh[n * 32 + lane]);  // ch 2*lane, 2*lane+1
        float a1 = b1s[lane];
        #pragma unroll
        for (int j = 0; j < 32; j++) {
            float vx = __shfl_sync(0xffffffffu, x.x, j);
            float vy = __shfl_sync(0xffffffffu, x.y, j);
            a1 += vx * W1s[(2 * j)     * HH + lane];
            a1 += vy * W1s[(2 * j + 1) * HH + lane];
        }
        a1 = (a1 > 0.f) ? a1 : 0.01f * a1;

        float a2 = b2s[lane];
        #pragma unroll
        for (int k = 0; k < 32; k++)
            a2 += __shfl_sync(0xffffffffu, a1, k) * W2s[k * HH + lane];
        a2 = (a2 > 0.f) ? a2 : 0.01f * a2;

        float p = a2 * W3s[lane];
        #pragma unroll
        for (int o = 16; o > 0; o >>= 1) p += __shfl_xor_sync(0xffffffffu, p, o);

        if (lane == 0) {
            float z = p + b3s;
            float sp = fmaxf(z, 0.f) + log1pf(expf(-fabsf(z)));  // stable softplus
            out[n] = sp;
            lsum += sp;
        }
    }
    if (lane == 0) wsum[warp] = lsum;
    __syncthreads();
    if (t == 0) atomicAdd(&g_sum, wsum[0] + wsum[1] + wsum[2] + wsum[3]);
}

__global__ void k_norm(float* __restrict__ out) {
    int i = blockIdx.x * blockDim.x + threadIdx.x;
    if (i < NN) {
        float r = __frcp_rn(g_sum + 1e-20f);
        out[i] = out[i] * r;
    }
}

// ---------------- launch ------------------------------------------------------

extern "C" void kernel_launch(void* const* d_in, const int* in_sizes, int n_in,
                              void* d_out, int out_size) {
    const float* state = (const float*)d_in[0];
    const int*   ei    = (const int*)  d_in[1];   // [2, E]
    const float* Wg    = (const float*)d_in[2];
    const float* bg    = (const float*)d_in[3];
    const float* W1    = (const float*)d_in[4];
    const float* b1    = (const float*)d_in[5];
    const float* W2    = (const float*)d_in[6];
    const float* b2    = (const float*)d_in[7];
    const float* W3    = (const float*)d_in[8];
    const float* b3    = (const float*)d_in[9];
    float* out = (float*)d_out;

    const int* row = ei;        // sources
    const int* col = ei + EE;   // targets

    // Launch order chosen so k_gather is launch #6 (ncu -s 5 -c 1 profiles it).
    k_xw     <<<NN / 8,   256>>>(state, Wg);     // (1) also zeroes g_cnt/g_sum
    k_count  <<<EE / 4 / 256, 256>>>((const int4*)col);           // (2)
    k_scan1  <<<SCAN_BLKS, 1024>>>();                             // (3)
    k_scan2  <<<1, 128>>>();                                      // (4)
    k_scatter<<<EE / 4 / 256, 256>>>((const int4*)row, (const int4*)col); // (5)
    k_gather <<<NN / 8,   256>>>(state, bg);                      // (6) profiled
    k_mlp    <<<592, 128>>>(W1, b1, W2, b2, W3, b3, out);         // (7)
    k_norm   <<<NN / 256, 256>>>(out);                            // (8)
}

// round 15
// speedup vs baseline: 1.6727x; 1.0536x over previous
#include <cuda_runtime.h>
#include <cuda_fp16.h>
#include <math.h>

// Problem constants (fixed shapes per reference)
#define NN 98304      // total nodes = B * ACT
#define CC 64         // channels
#define EE 1572864    // edges
#define HH 32         // hidden
#define SCAN_BLKS 96  // NN / 1024

// ---------------- static device scratch (no allocation allowed) --------------
__device__ int     g_cnt[NN];        // in-degree (excl. self loop)
__device__ float   g_dinv[NN];       // rsqrt(deg+1)
__device__ int     g_rowptr[NN];     // CSR offsets, BLOCK-LOCAL (add g_boff[i>>10])
__device__ int     g_pos[NN];        // scatter cursors, BLOCK-LOCAL
__device__ int     g_src[EE];        // CSR source-node indices
__device__ int     g_btot[SCAN_BLKS];// per-block totals
__device__ int     g_boff[SCAN_BLKS];// per-block exclusive offsets
__device__ int     g_scan_ctr;       // last-block detector for fused scan
__device__ __half2 g_xwh[NN * 32];   // state @ W_gcn, fp16 pairs (ch 2l,2l+1)
__device__ float   g_sum;            // global softplus sum

// ---------------- kernels ----------------------------------------------------

// xw = state @ W_gcn ; warp-per-node, W in SMEM. Runs FIRST; also zeroes
// g_cnt / g_sum / g_scan_ctr (no dependence on edge data).
__global__ void k_xw(const float* __restrict__ state, const float* __restrict__ Wg) {
    __shared__ float Ws[CC * CC];   // 16 KB, row-major W[k][c]
    int t = threadIdx.x;
    int gid = blockIdx.x * blockDim.x + t;
    if (gid < NN) g_cnt[gid] = 0;
    if (gid == 0) { g_sum = 0.0f; g_scan_ctr = 0; }
    for (int i = t; i < CC * CC; i += blockDim.x) Ws[i] = Wg[i];
    __syncthreads();
    const float2* Ws2 = (const float2*)Ws;   // Ws2[k*32 + l] = (W[k][2l], W[k][2l+1])
    int lane = t & 31;
    int n = blockIdx.x * (blockDim.x >> 5) + (t >> 5);
    float x0 = state[n * CC + lane];
    float x1 = state[n * CC + 32 + lane];
    float a0 = 0.f, a1 = 0.f;
    #pragma unroll
    for (int k = 0; k < 32; k++) {
        float v = __shfl_sync(0xffffffffu, x0, k);
        float2 w = Ws2[k * 32 + lane];
        a0 += v * w.x;
        a1 += v * w.y;
    }
    #pragma unroll
    for (int k = 0; k < 32; k++) {
        float v = __shfl_sync(0xffffffffu, x1, k);
        float2 w = Ws2[(k + 32) * 32 + lane];
        a0 += v * w.x;
        a1 += v * w.y;
    }
    g_xwh[n * 32 + lane] = __floats2half2_rn(a0, a1);
}

// 4 edges per thread via one int4 load; atomicAdd w/o return -> REDG.
__global__ void k_count(const int4* __restrict__ col4) {
    int e = blockIdx.x * blockDim.x + threadIdx.x;
    if (e < EE / 4) {
        int4 c = col4[e];
        atomicAdd(&g_cnt[c.x], 1);
        atomicAdd(&g_cnt[c.y], 1);
        atomicAdd(&g_cnt[c.z], 1);
        atomicAdd(&g_cnt[c.w], 1);
    }
}

// Per-block exclusive scan (1024 elems/block) + dinv + cursors; the LAST
// block to finish also scans the 96 block totals -> g_boff (fused scan2).
__global__ void k_scan1() {
    __shared__ int wsum[32];
    __shared__ int s2[128];
    __shared__ int isLast;
    int t = threadIdx.x;
    int lane = t & 31, warp = t >> 5;
    int i = blockIdx.x * 1024 + t;
    int c = g_cnt[i];
    int x = c;
    #pragma unroll
    for (int off = 1; off < 32; off <<= 1) {
        int y = __shfl_up_sync(0xffffffffu, x, off);
        if (lane >= off) x += y;
    }
    if (lane == 31) wsum[warp] = x;
    __syncthreads();
    if (warp == 0) {
        int s = wsum[lane];
        #pragma unroll
        for (int off = 1; off < 32; off <<= 1) {
            int y = __shfl_up_sync(0xffffffffu, s, off);
            if (lane >= off) s += y;
        }
        wsum[lane] = s;   // inclusive over warps
    }
    __syncthreads();
    int excl = x - c + (warp > 0 ? wsum[warp - 1] : 0);
    g_rowptr[i] = excl;                       // block-local
    g_pos[i]    = excl;                       // block-local cursor
    g_dinv[i]   = rsqrtf((float)(c + 1));
    if (t == 1023) g_btot[blockIdx.x] = excl + c;

    // last-block fused scan of block totals
    __threadfence();
    if (t == 0) {
        int d = atomicAdd(&g_scan_ctr, 1);
        isLast = (d == SCAN_BLKS - 1) ? 1 : 0;
    }
    __syncthreads();
    if (isLast) {
        int v = (t < SCAN_BLKS) ? g_btot[t] : 0;
        if (t < 128) s2[t] = v;
        __syncthreads();
        for (int off = 1; off < 128; off <<= 1) {
            int a = (t >= off && t < 128) ? s2[t - off] : 0;
            __syncthreads();
            if (t < 128) s2[t] += a;
            __syncthreads();
        }
        if (t < SCAN_BLKS) g_boff[t] = s2[t] - v;  // exclusive
    }
}

// 4 edges per thread; local cursor + block offset -> global CSR slot.
__global__ void k_scatter(const int4* __restrict__ row4, const int4* __restrict__ col4) {
    int e = blockIdx.x * blockDim.x + threadIdx.x;
    if (e < EE / 4) {
        int4 r = row4[e];
        int4 c = col4[e];
        g_src[atomicAdd(&g_pos[c.x], 1) + g_boff[c.x >> 10]] = r.x;
        g_src[atomicAdd(&g_pos[c.y], 1) + g_boff[c.y >> 10]] = r.y;
        g_src[atomicAdd(&g_pos[c.z], 1) + g_boff[c.z >> 10]] = r.z;
        g_src[atomicAdd(&g_pos[c.w], 1) + g_boff[c.w >> 10]] = r.w;
    }
}

// FUSED gather + GCN epilogue + MLP + softplus. Warp per node (grid-stride),
// no atomics in gather, h never touches memory (stays in 2 regs/lane).
__global__ void k_gmlp(const float* __restrict__ state, const float* __restrict__ b_gcn,
                       const float* __restrict__ W1, const float* __restrict__ b1,
                       const float* __restrict__ W2, const float* __restrict__ b2,
                       const float* __restrict__ W3, const float* __restrict__ b3,
                       float* __restrict__ out) {
    __shared__ float W1s[CC * HH];   // 8 KB
    __shared__ float W2s[HH * HH];   // 4 KB
    __shared__ float W3s[HH], b1s[HH], b2s[HH];
    __shared__ float b3s;
    __shared__ float wsum[8];
    int t = threadIdx.x;
    for (int i = t; i < CC * HH; i += 256) W1s[i] = W1[i];
    for (int i = t; i < HH * HH; i += 256) W2s[i] = W2[i];
    if (t < HH) { W3s[t] = W3[t]; b1s[t] = b1[t]; b2s[t] = b2[t]; }
    if (t == 0) b3s = b3[0];
    __syncthreads();

    int lane = t & 31, warp = t >> 5;
    int gw = blockIdx.x * 8 + warp;
    int nwarps = gridDim.x * 8;
    float lsum = 0.f;

    for (int n = gw; n < NN; n += nwarps) {
        // ---- gather ----
        int j   = g_rowptr[n] + g_boff[n >> 10];
        int end = (n == NN - 1) ? EE : (g_rowptr[n + 1] + g_boff[(n + 1) >> 10]);
        float acc0 = 0.f, acc1 = 0.f;
        for (; j + 4 <= end; j += 4) {
            int sA = g_src[j];
            int sB = g_src[j + 1];
            int sC = g_src[j + 2];
            int sD = g_src[j + 3];
            float wA = g_dinv[sA];
            float wB = g_dinv[sB];
            float wC = g_dinv[sC];
            float wD = g_dinv[sD];
            float2 vA = __half22float2(g_xwh[sA * 32 + lane]);
            float2 vB = __half22float2(g_xwh[sB * 32 + lane]);
            float2 vC = __half22float2(g_xwh[sC * 32 + lane]);
            float2 vD = __half22float2(g_xwh[sD * 32 + lane]);
            acc0 += wA * vA.x + wB * vB.x + wC * vC.x + wD * vD.x;
            acc1 += wA * vA.y + wB * vB.y + wC * vC.y + wD * vD.y;
        }
        for (; j < end; j++) {
            int s = g_src[j];
            float w = g_dinv[s];
            float2 v = __half22float2(g_xwh[s * 32 + lane]);
            acc0 += w * v.x;
            acc1 += w * v.y;
        }
        // ---- GCN epilogue: h channels 2l,2l+1 in (o0,o1) ----
        float dn = g_dinv[n];
        float2 self = __half22float2(g_xwh[n * 32 + lane]);
        float2 b  = ((const float2*)b_gcn)[lane];
        float2 st = ((const float2*)state)[n * 32 + lane];
        float o0 = dn * (acc0 + dn * self.x) + b.x;
        float o1 = dn * (acc1 + dn * self.y) + b.y;
        o0 = fmaxf(o0, 0.f) + st.x;
        o1 = fmaxf(o1, 0.f) + st.y;
        // ---- MLP 64->32->32->1 ----
        float a1 = b1s[lane];
        #pragma unroll
        for (int k = 0; k < 32; k++) {
            float vx = __shfl_sync(0xffffffffu, o0, k);
            float vy = __shfl_sync(0xffffffffu, o1, k);
            a1 += vx * W1s[(2 * k)     * HH + lane];
            a1 += vy * W1s[(2 * k + 1) * HH + lane];
        }
        a1 = (a1 > 0.f) ? a1 : 0.01f * a1;

        float a2 = b2s[lane];
        #pragma unroll
        for (int k = 0; k < 32; k++)
            a2 += __shfl_sync(0xffffffffu, a1, k) * W2s[k * HH + lane];
        a2 = (a2 > 0.f) ? a2 : 0.01f * a2;

        float p = a2 * W3s[lane];
        #pragma unroll
        for (int o = 16; o > 0; o >>= 1) p += __shfl_xor_sync(0xffffffffu, p, o);

        if (lane == 0) {
            float z = p + b3s;
            float sp = fmaxf(z, 0.f) + log1pf(expf(-fabsf(z)));  // stable softplus
            out[n] = sp;
            lsum += sp;
        }
    }
    if (lane == 0) wsum[warp] = lsum;
    __syncthreads();
    if (t == 0) {
        float s = 0.f;
        #pragma unroll
        for (int w = 0; w < 8; w++) s += wsum[w];
        atomicAdd(&g_sum, s);
    }
}

__global__ void k_norm(float* __restrict__ out) {
    int i = blockIdx.x * blockDim.x + threadIdx.x;
    if (i < NN) {
        float r = __frcp_rn(g_sum + 1e-20f);
        out[i] = out[i] * r;
    }
}

// ---------------- launch ------------------------------------------------------

extern "C" void kernel_launch(void* const* d_in, const int* in_sizes, int n_in,
                              void* d_out, int out_size) {
    const float* state = (const float*)d_in[0];
    const int*   ei    = (const int*)  d_in[1];   // [2, E]
    const float* Wg    = (const float*)d_in[2];
    const float* bg    = (const float*)d_in[3];
    const float* W1    = (const float*)d_in[4];
    const float* b1    = (const float*)d_in[5];
    const float* W2    = (const float*)d_in[6];
    const float* b2    = (const float*)d_in[7];
    const float* W3    = (const float*)d_in[8];
    const float* b3    = (const float*)d_in[9];
    float* out = (float*)d_out;

    const int* row = ei;        // sources
    const int* col = ei + EE;   // targets

    // k_scatter is our 4th kernel -> profiled by ncu (-s 5 -c 1 incl. 2 harness kernels).
    k_xw     <<<NN / 8,   256>>>(state, Wg);                      // (1) + zero cnt/sum/ctr
    k_count  <<<EE / 4 / 256, 256>>>((const int4*)col);           // (2)
    k_scan1  <<<SCAN_BLKS, 1024>>>();                             // (3) fused scan2
    k_scatter<<<EE / 4 / 256, 256>>>((const int4*)row, (const int4*)col); // (4) profiled
    k_gmlp   <<<1184, 256>>>(state, bg, W1, b1, W2, b2, W3, b3, out);     // (5)
    k_norm   <<<NN / 256, 256>>>(out);                            // (6)
}